// round 13
// baseline (speedup 1.0000x reference)
#include <cuda_runtime.h>
#include <cstdint>

#define W_  256
#define H_  256
#define C_  256
#define HW_ 65536
#define B_  4
#define BN  4096
#define OC  128
#define NT  256
#define NTILES 1024            // B_*HW_/NT
#define GRID_GEMM 148
#define AFRAG_BYTES 131072
#define CHUNK_BYTES 32768      // 32k x 256hw x 4B
#define GEMM_SMEM (AFRAG_BYTES + 3*CHUNK_BYTES)   // 229376

__device__ float g_G[(size_t)B_ * HW_ * OC];   // [b][hw][o]
__device__ float g_pooled[BN * OC];

__device__ __forceinline__ uint32_t f2tf(float x) {
    uint32_t r; asm("cvt.rna.tf32.f32 %0, %1;" : "=r"(r) : "f"(x)); return r;
}
__device__ __forceinline__ uint32_t s2u(const void* p) {
    uint32_t a;
    asm("{ .reg .u64 t; cvta.to.shared.u64 t, %1; cvt.u32.u64 %0, t; }" : "=r"(a) : "l"(p));
    return a;
}
__device__ __forceinline__ void mma8(float* d, uint4 a, uint32_t b0, uint32_t b1) {
    asm volatile("mma.sync.aligned.m16n8k8.row.col.f32.tf32.tf32.f32 "
        "{%0,%1,%2,%3}, {%4,%5,%6,%7}, {%8,%9}, {%0,%1,%2,%3};"
        : "+f"(d[0]), "+f"(d[1]), "+f"(d[2]), "+f"(d[3])
        : "r"(a.x), "r"(a.y), "r"(a.z), "r"(a.w), "r"(b0), "r"(b1));
}

// issue one k32 x hw256 feature chunk via cp.async (XOR-swizzled), commit group.
__device__ __forceinline__ void issue_chunk(const float* __restrict__ f,
                                            int t, int c, uint32_t dst_base, int tid)
{
    if (t < NTILES) {
        const int b = t >> 8, hw0 = (t & 255) * NT;
        const int row = tid >> 4;
        const int col0 = (tid & 15) * 16;
        const float* src = f + ((size_t)(b * C_ + c * 32 + row)) * HW_ + hw0 + col0;
        #pragma unroll
        for (int j = 0; j < 4; j++) {
            const int col  = col0 + j * 4;
            const int colp = col ^ ((row & 3) << 3);
            const uint32_t dst = dst_base + ((uint32_t)(row * 256 + colp)) * 4u;
            asm volatile("cp.async.cg.shared.global [%0], [%1], 16;"
                         :: "r"(dst), "l"(src + j * 4) : "memory");
        }
    }
    asm volatile("cp.async.commit_group;" ::: "memory");
}

// ============================================================================
// GEMM: 512 threads (16 warps), persistent. CTA tile m128 x n256,
// warp tile m64 x n32 (B reuse x4 -> 36 issues per 16 mma).
// A frags in smem; B cp.async 3-stage ring; rna->tf32 at LDS->mma boundary.
// ============================================================================
__global__ __launch_bounds__(512, 1)
void gemm_kernel(const float* __restrict__ features, const float* __restrict__ Wc)
{
    extern __shared__ __align__(16) char dsm[];
    const uint32_t bs_u = s2u(dsm) + AFRAG_BYTES;

    const int tid = threadIdx.x, wid = tid >> 5, lane = tid & 31;
    const int g = lane >> 2, t4 = lane & 3;
    const int mg = wid & 1, ng = wid >> 1;        // m-group (o 64), n-group (hw 32)

    // start streaming chunks 0..2 immediately (hide DRAM under A build)
    int tn = blockIdx.x, cn = 0;
    #pragma unroll
    for (int i = 0; i < 3; i++) {
        issue_chunk(features, tn, cn, bs_u + i * CHUNK_BYTES, tid);
        if (++cn == 8) { cn = 0; tn += GRID_GEMM; }
    }

    // A fragments: warps 0..7; warp w builds m16 strip w (o = 16w..16w+15)
    if (wid < 8) {
        const int o0 = wid * 16;
        for (int k = 0; k < 32; k++) {
            uint4 a;
            a.x = f2tf(__ldg(&Wc[(o0 + g    ) * 256 + k * 8 + t4    ]));
            a.y = f2tf(__ldg(&Wc[(o0 + g + 8) * 256 + k * 8 + t4    ]));
            a.z = f2tf(__ldg(&Wc[(o0 + g    ) * 256 + k * 8 + t4 + 4]));
            a.w = f2tf(__ldg(&Wc[(o0 + g + 8) * 256 + k * 8 + t4 + 4]));
            *(uint4*)(dsm + (((k * 8 + wid) * 32) + lane) * 16) = a;
        }
    }

    int bufi = 0;
    for (int t = blockIdx.x; t < NTILES; t += GRID_GEMM) {
        float acc[4][4][4];
        #pragma unroll
        for (int mi = 0; mi < 4; mi++)
            #pragma unroll
            for (int ni = 0; ni < 4; ni++)
                #pragma unroll
                for (int q = 0; q < 4; q++) acc[mi][ni][q] = 0.f;

        #pragma unroll
        for (int c = 0; c < 8; c++) {
            asm volatile("cp.async.wait_group 2;" ::: "memory");
            __syncthreads();                       // chunk ready (and A frags on c==0)
            const float* bb = (const float*)(dsm + AFRAG_BYTES + bufi * CHUNK_BYTES);
            #pragma unroll
            for (int kkl = 0; kkl < 4; kkl++) {
                const int ka = c * 4 + kkl;
                uint4 a[4];
                #pragma unroll
                for (int mi = 0; mi < 4; mi++)
                    a[mi] = *(const uint4*)(dsm + ((ka * 8 + mg * 4 + mi) * 32 + lane) * 16);
                #pragma unroll
                for (int ni = 0; ni < 4; ni++) {
                    const int colp = (ng * 32 + ni * 8 + g) ^ (t4 << 3);
                    // round-to-nearest tf32 (raw bits would truncate -> biased)
                    const uint32_t b0 = f2tf(bb[(kkl * 8 + t4    ) * 256 + colp]);
                    const uint32_t b1 = f2tf(bb[(kkl * 8 + t4 + 4) * 256 + colp]);
                    #pragma unroll
                    for (int mi = 0; mi < 4; mi++) mma8(acc[mi][ni], a[mi], b0, b1);
                }
            }
            __syncthreads();                       // done reading this buffer
            issue_chunk(features, tn, cn, bs_u + bufi * CHUNK_BYTES, tid);
            if (++cn == 8) { cn = 0; tn += GRID_GEMM; }
            bufi = (bufi == 2) ? 0 : bufi + 1;
        }
        // epilogue: D -> g_G[b][hw][o]
        {
            const int b = t >> 8, hw0 = (t & 255) * NT;
            float* gb = g_G + (size_t)b * HW_ * OC;
            #pragma unroll
            for (int mi = 0; mi < 4; mi++)
                #pragma unroll
                for (int ni = 0; ni < 4; ni++) {
                    const int o  = mg * 64 + mi * 16 + g;
                    const int hw = hw0 + ng * 32 + ni * 8 + 2 * t4;
                    float* p = gb + (size_t)hw * OC + o;
                    p[0]      = acc[mi][ni][0];
                    p[OC]     = acc[mi][ni][1];
                    p[8]      = acc[mi][ni][2];
                    p[OC + 8] = acc[mi][ni][3];
                }
        }
    }
}

// ============================================================================
// Gather: bilinear on G + bias + relu + 7x7 mean. Block = vertex, thread = o.
// ============================================================================
__global__ __launch_bounds__(128)
void gather_pool_kernel(const float* __restrict__ vertices, const float* __restrict__ bc)
{
    const int bid = blockIdx.x, o = threadIdx.x, b = bid >> 10;
    const float fx = vertices[bid * 2] - 3.5f, fy = vertices[bid * 2 + 1] - 3.5f;
    int ix = (int)floorf(fx), iy = (int)floorf(fy);
    const float lx = fx - ix, ly = fy - iy;
    ix = max(0, min(ix, W_ - 8)); iy = max(0, min(iy, H_ - 8));
    const float hx = 1.f - lx, hy = 1.f - ly;
    const float w00 = hy * hx, w01 = hy * lx, w10 = ly * hx, w11 = ly * lx;
    const float bias = __ldg(&bc[o]);

    const float* base = g_G + ((size_t)b * HW_ + (size_t)iy * W_ + ix) * OC + o;
    float prev[8], cur[8], acc = 0.f;
    #pragma unroll
    for (int r = 0; r < 8; r++) {
        #pragma unroll
        for (int c = 0; c < 8; c++) cur[c] = __ldg(base + ((size_t)r * W_ + c) * OC);
        if (r > 0) {
            #pragma unroll
            for (int px = 0; px < 7; px++) {
                const float v = w00 * prev[px] + w01 * prev[px + 1]
                              + w10 * cur[px]  + w11 * cur[px + 1] + bias;
                acc += fmaxf(v, 0.f);
            }
        }
        #pragma unroll
        for (int c = 0; c < 8; c++) prev[c] = cur[c];
    }
    g_pooled[bid * OC + o] = acc * (1.0f / 49.0f);
}

// ============================================================================
// MLP + heads. 8 vertices/block (512 blocks), 256 threads, SPAD 12 (18.4 KB).
// h1: 4 outputs x 2 vertices per thread; h2: 4 outputs x 1 vertex.
// ============================================================================
#define MBV 8
#define SPAD 12
__global__ __launch_bounds__(256)
void mlp_kernel(const float* __restrict__ W1, const float* __restrict__ b1,
                const float* __restrict__ W2, const float* __restrict__ b2,
                const float* __restrict__ Wa, const float* __restrict__ ba,
                const float* __restrict__ Wr, const float* __restrict__ br,
                const float* __restrict__ Ww, const float* __restrict__ bw,
                float* __restrict__ out)
{
    extern __shared__ __align__(16) float ms[];
    float* sP = ms;                 // [128][SPAD] pooled (k-major), later h2T
    float* sH = ms + 128 * SPAD;    // [256][SPAD] h1T

    const int tid = threadIdx.x, base = blockIdx.x * MBV;

    for (int e = tid; e < MBV * 128; e += 256) {
        const int v = e >> 7, k = e & 127;
        sP[k * SPAD + v] = g_pooled[(base + v) * 128 + k];
    }
    __syncthreads();

    // ---- h1: thread = (oq 64, vq 4): outputs oq*4..+3, vertices vq*2..+1 ----
    {
        const int oq = tid >> 2, vq = tid & 3;
        float acc[4][2];
        #pragma unroll
        for (int r = 0; r < 4; r++) { acc[r][0] = 0.f; acc[r][1] = 0.f; }
        #pragma unroll 2
        for (int k4 = 0; k4 < 32; ++k4) {
            float4 wv[4];
            #pragma unroll
            for (int r = 0; r < 4; r++)
                wv[r] = __ldg((const float4*)(W1 + (oq * 4 + r) * 128 + k4 * 4));
            #pragma unroll
            for (int u = 0; u < 4; ++u) {
                const int k = k4 * 4 + u;
                const float2 va = *(const float2*)&sP[k * SPAD + vq * 2];
                #pragma unroll
                for (int r = 0; r < 4; r++) {
                    const float w = (u == 0) ? wv[r].x : (u == 1) ? wv[r].y
                                  : (u == 2) ? wv[r].z : wv[r].w;
                    acc[r][0] += w * va.x; acc[r][1] += w * va.y;
                }
            }
        }
        #pragma unroll
        for (int r = 0; r < 4; r++) {
            const int o = oq * 4 + r;
            const float bb = __ldg(&b1[o]);
            float2 r0;
            r0.x = fmaxf(acc[r][0] + bb, 0.f);
            r0.y = fmaxf(acc[r][1] + bb, 0.f);
            *(float2*)&sH[o * SPAD + vq * 2] = r0;
        }
    }
    __syncthreads();

    // ---- h2: thread = (oq2 32, vq2 8): outputs oq2*4..+3, vertex vq2 ----
    {
        const int oq2 = tid >> 3, vq2 = tid & 7;
        float acc2[4] = {0.f, 0.f, 0.f, 0.f};
        #pragma unroll 2
        for (int k4 = 0; k4 < 64; ++k4) {
            float4 wv[4];
            #pragma unroll
            for (int r = 0; r < 4; r++)
                wv[r] = __ldg((const float4*)(W2 + (oq2 * 4 + r) * 256 + k4 * 4));
            #pragma unroll
            for (int u = 0; u < 4; ++u) {
                const int k = k4 * 4 + u;
                const float va = sH[k * SPAD + vq2];
                #pragma unroll
                for (int r = 0; r < 4; r++) {
                    const float w = (u == 0) ? wv[r].x : (u == 1) ? wv[r].y
                                  : (u == 2) ? wv[r].z : wv[r].w;
                    acc2[r] += w * va;
                }
            }
        }
        __syncthreads();   // all h1 reads of sP done; reuse sP as h2T
        #pragma unroll
        for (int r = 0; r < 4; r++) {
            const int o = oq2 * 4 + r;
            sP[o * SPAD + vq2] = fmaxf(acc2[r] + __ldg(&b2[o]), 0.f);
        }
    }
    __syncthreads();

    // ---- heads ----
    if (tid < MBV * 4) {
        const int v = tid >> 2, hd = tid & 3;
        const float* wr; float bias;
        if      (hd == 0) { wr = Wa;       bias = __ldg(&ba[0]); }
        else if (hd == 1) { wr = Wa + 128; bias = __ldg(&ba[1]); }
        else if (hd == 2) { wr = Wr;       bias = __ldg(&br[0]); }
        else              { wr = Ww;       bias = __ldg(&bw[0]); }
        float s = bias;
        #pragma unroll 4
        for (int k = 0; k < 128; k++) s = fmaf(__ldg(&wr[k]), sP[k * SPAD + v], s);
        const int gidx = base + v;
        if      (hd <  2) out[gidx * 2 + hd] = s;
        else if (hd == 2) out[2 * BN + gidx] = s;
        else              out[3 * BN + gidx] = s;
    }
}

// ============================================================================
extern "C" void kernel_launch(void* const* d_in, const int* in_sizes, int n_in,
                              void* d_out, int out_size)
{
    const float* features = (const float*)d_in[0];
    const float* vertices = (const float*)d_in[1];
    const float* Wc = (const float*)d_in[2];
    const float* bc = (const float*)d_in[3];
    const float* W1 = (const float*)d_in[4];
    const float* b1 = (const float*)d_in[5];
    const float* W2 = (const float*)d_in[6];
    const float* b2 = (const float*)d_in[7];
    const float* Wa = (const float*)d_in[8];
    const float* ba = (const float*)d_in[9];
    const float* Wr = (const float*)d_in[10];
    const float* br = (const float*)d_in[11];
    const float* Ww = (const float*)d_in[12];
    const float* bw = (const float*)d_in[13];
    float* out = (float*)d_out;

    cudaFuncSetAttribute(gemm_kernel, cudaFuncAttributeMaxDynamicSharedMemorySize, GEMM_SMEM);

    gemm_kernel<<<GRID_GEMM, 512, GEMM_SMEM>>>(features, Wc);
    gather_pool_kernel<<<BN, 128>>>(vertices, bc);
    mlp_kernel<<<BN / MBV, 256, (128 + 256) * SPAD * 4>>>(W1, b1, W2, b2, Wa, ba, Wr, br, Ww, bw, out);
}

// round 14
// speedup vs baseline: 1.0036x; 1.0036x over previous
#include <cuda_runtime.h>
#include <cstdint>

#define W_  256
#define H_  256
#define C_  256
#define HW_ 65536
#define B_  4
#define BN  4096
#define OC  128
#define NT  256
#define NTILES 1024            // B_*HW_/NT
#define GRID_GEMM 148
#define AFRAG_BYTES 131072
#define CHUNK_BYTES 32768      // 32k x 256hw x 4B
#define GEMM_SMEM (AFRAG_BYTES + 3*CHUNK_BYTES)   // 229376

__device__ float g_G[(size_t)B_ * HW_ * OC];   // [b][hw][o]
__device__ float g_pooled[BN * OC];

__device__ __forceinline__ uint32_t f2tf(float x) {
    uint32_t r; asm("cvt.rna.tf32.f32 %0, %1;" : "=r"(r) : "f"(x)); return r;
}
__device__ __forceinline__ uint32_t s2u(const void* p) {
    uint32_t a;
    asm("{ .reg .u64 t; cvta.to.shared.u64 t, %1; cvt.u32.u64 %0, t; }" : "=r"(a) : "l"(p));
    return a;
}
__device__ __forceinline__ void mma8(float* d, uint4 a, uint32_t b0, uint32_t b1) {
    asm volatile("mma.sync.aligned.m16n8k8.row.col.f32.tf32.tf32.f32 "
        "{%0,%1,%2,%3}, {%4,%5,%6,%7}, {%8,%9}, {%0,%1,%2,%3};"
        : "+f"(d[0]), "+f"(d[1]), "+f"(d[2]), "+f"(d[3])
        : "r"(a.x), "r"(a.y), "r"(a.z), "r"(a.w), "r"(b0), "r"(b1));
}

// issue one k32 x hw256 feature chunk via cp.async (XOR-swizzled), commit group.
__device__ __forceinline__ void issue_chunk(const float* __restrict__ f,
                                            int t, int c, uint32_t dst_base, int tid)
{
    if (t < NTILES) {
        const int b = t >> 8, hw0 = (t & 255) * NT;
        const int row = tid >> 4;
        const int col0 = (tid & 15) * 16;
        const float* src = f + ((size_t)(b * C_ + c * 32 + row)) * HW_ + hw0 + col0;
        #pragma unroll
        for (int j = 0; j < 4; j++) {
            const int col  = col0 + j * 4;
            const int colp = col ^ ((row & 3) << 3);
            const uint32_t dst = dst_base + ((uint32_t)(row * 256 + colp)) * 4u;
            asm volatile("cp.async.cg.shared.global [%0], [%1], 16;"
                         :: "r"(dst), "l"(src + j * 4) : "memory");
        }
    }
    asm volatile("cp.async.commit_group;" ::: "memory");
}

// ============================================================================
// GEMM (R13 config, measured 138.9us): 512 threads, CTA m128 x n256,
// warp tile m64 x n32. A frags in smem; B cp.async 3-stage ring.
// ============================================================================
__global__ __launch_bounds__(512, 1)
void gemm_kernel(const float* __restrict__ features, const float* __restrict__ Wc)
{
    extern __shared__ __align__(16) char dsm[];
    const uint32_t bs_u = s2u(dsm) + AFRAG_BYTES;

    const int tid = threadIdx.x, wid = tid >> 5, lane = tid & 31;
    const int g = lane >> 2, t4 = lane & 3;
    const int mg = wid & 1, ng = wid >> 1;        // m-group (o 64), n-group (hw 32)

    int tn = blockIdx.x, cn = 0;
    #pragma unroll
    for (int i = 0; i < 3; i++) {
        issue_chunk(features, tn, cn, bs_u + i * CHUNK_BYTES, tid);
        if (++cn == 8) { cn = 0; tn += GRID_GEMM; }
    }

    if (wid < 8) {
        const int o0 = wid * 16;
        for (int k = 0; k < 32; k++) {
            uint4 a;
            a.x = f2tf(__ldg(&Wc[(o0 + g    ) * 256 + k * 8 + t4    ]));
            a.y = f2tf(__ldg(&Wc[(o0 + g + 8) * 256 + k * 8 + t4    ]));
            a.z = f2tf(__ldg(&Wc[(o0 + g    ) * 256 + k * 8 + t4 + 4]));
            a.w = f2tf(__ldg(&Wc[(o0 + g + 8) * 256 + k * 8 + t4 + 4]));
            *(uint4*)(dsm + (((k * 8 + wid) * 32) + lane) * 16) = a;
        }
    }

    int bufi = 0;
    for (int t = blockIdx.x; t < NTILES; t += GRID_GEMM) {
        float acc[4][4][4];
        #pragma unroll
        for (int mi = 0; mi < 4; mi++)
            #pragma unroll
            for (int ni = 0; ni < 4; ni++)
                #pragma unroll
                for (int q = 0; q < 4; q++) acc[mi][ni][q] = 0.f;

        #pragma unroll
        for (int c = 0; c < 8; c++) {
            asm volatile("cp.async.wait_group 2;" ::: "memory");
            __syncthreads();
            const float* bb = (const float*)(dsm + AFRAG_BYTES + bufi * CHUNK_BYTES);
            #pragma unroll
            for (int kkl = 0; kkl < 4; kkl++) {
                const int ka = c * 4 + kkl;
                uint4 a[4];
                #pragma unroll
                for (int mi = 0; mi < 4; mi++)
                    a[mi] = *(const uint4*)(dsm + ((ka * 8 + mg * 4 + mi) * 32 + lane) * 16);
                #pragma unroll
                for (int ni = 0; ni < 4; ni++) {
                    const int colp = (ng * 32 + ni * 8 + g) ^ (t4 << 3);
                    const uint32_t b0 = f2tf(bb[(kkl * 8 + t4    ) * 256 + colp]);
                    const uint32_t b1 = f2tf(bb[(kkl * 8 + t4 + 4) * 256 + colp]);
                    #pragma unroll
                    for (int mi = 0; mi < 4; mi++) mma8(acc[mi][ni], a[mi], b0, b1);
                }
            }
            __syncthreads();
            issue_chunk(features, tn, cn, bs_u + bufi * CHUNK_BYTES, tid);
            if (++cn == 8) { cn = 0; tn += GRID_GEMM; }
            bufi = (bufi == 2) ? 0 : bufi + 1;
        }
        {
            const int b = t >> 8, hw0 = (t & 255) * NT;
            float* gb = g_G + (size_t)b * HW_ * OC;
            #pragma unroll
            for (int mi = 0; mi < 4; mi++)
                #pragma unroll
                for (int ni = 0; ni < 4; ni++) {
                    const int o  = mg * 64 + mi * 16 + g;
                    const int hw = hw0 + ng * 32 + ni * 8 + 2 * t4;
                    float* p = gb + (size_t)hw * OC + o;
                    p[0]      = acc[mi][ni][0];
                    p[OC]     = acc[mi][ni][1];
                    p[8]      = acc[mi][ni][2];
                    p[OC + 8] = acc[mi][ni][3];
                }
        }
    }
}

// ============================================================================
// Gather: bilinear on G + bias + relu + 7x7 mean. Block = vertex, thread = o.
// ============================================================================
__global__ __launch_bounds__(128)
void gather_pool_kernel(const float* __restrict__ vertices, const float* __restrict__ bc)
{
    const int bid = blockIdx.x, o = threadIdx.x, b = bid >> 10;
    const float fx = vertices[bid * 2] - 3.5f, fy = vertices[bid * 2 + 1] - 3.5f;
    int ix = (int)floorf(fx), iy = (int)floorf(fy);
    const float lx = fx - ix, ly = fy - iy;
    ix = max(0, min(ix, W_ - 8)); iy = max(0, min(iy, H_ - 8));
    const float hx = 1.f - lx, hy = 1.f - ly;
    const float w00 = hy * hx, w01 = hy * lx, w10 = ly * hx, w11 = ly * lx;
    const float bias = __ldg(&bc[o]);

    const float* base = g_G + ((size_t)b * HW_ + (size_t)iy * W_ + ix) * OC + o;
    float prev[8], cur[8], acc = 0.f;
    #pragma unroll
    for (int r = 0; r < 8; r++) {
        #pragma unroll
        for (int c = 0; c < 8; c++) cur[c] = __ldg(base + ((size_t)r * W_ + c) * OC);
        if (r > 0) {
            #pragma unroll
            for (int px = 0; px < 7; px++) {
                const float v = w00 * prev[px] + w01 * prev[px + 1]
                              + w10 * cur[px]  + w11 * cur[px + 1] + bias;
                acc += fmaxf(v, 0.f);
            }
        }
        #pragma unroll
        for (int c = 0; c < 8; c++) prev[c] = cur[c];
    }
    g_pooled[bid * OC + o] = acc * (1.0f / 49.0f);
}

// ============================================================================
// MLP + heads. 16 vertices/block, 512 threads (256 blocks, ~28 warps/SM).
// h1: thread = (o 256, vh 2) -> 8 vertices. h2: thread = (c2 128, vq 4) -> 4.
// smem (128+256)*SPAD*4 = 30,720 B.
// ============================================================================
#define MBV 16
#define SPAD 20
__global__ __launch_bounds__(512)
void mlp_kernel(const float* __restrict__ W1, const float* __restrict__ b1,
                const float* __restrict__ W2, const float* __restrict__ b2,
                const float* __restrict__ Wa, const float* __restrict__ ba,
                const float* __restrict__ Wr, const float* __restrict__ br,
                const float* __restrict__ Ww, const float* __restrict__ bw,
                float* __restrict__ out)
{
    extern __shared__ __align__(16) float ms[];
    float* sP = ms;                 // [128][SPAD] pooled (k-major), later h2T
    float* sH = ms + 128 * SPAD;    // [256][SPAD] h1T

    const int tid = threadIdx.x, base = blockIdx.x * MBV;

    for (int e = tid; e < MBV * 128; e += 512) {
        const int v = e >> 7, k = e & 127;
        sP[k * SPAD + v] = g_pooled[(base + v) * 128 + k];
    }
    __syncthreads();

    // ---- h1: thread = (o 256, vh 2): vertices vh*8..+7 ----
    {
        const int o = tid >> 1, vh = tid & 1;
        float acc[8];
        #pragma unroll
        for (int j = 0; j < 8; j++) acc[j] = 0.f;
        const float4* w1r = (const float4*)(W1 + o * 128);
        #pragma unroll 2
        for (int k4 = 0; k4 < 32; ++k4) {
            const float4 w4 = __ldg(&w1r[k4]);
            #pragma unroll
            for (int u = 0; u < 4; ++u) {
                const int k = k4 * 4 + u;
                const float w = (u == 0) ? w4.x : (u == 1) ? w4.y
                              : (u == 2) ? w4.z : w4.w;
                const float4 va = *(const float4*)&sP[k * SPAD + vh * 8];
                const float4 vb = *(const float4*)&sP[k * SPAD + vh * 8 + 4];
                acc[0] += w * va.x; acc[1] += w * va.y;
                acc[2] += w * va.z; acc[3] += w * va.w;
                acc[4] += w * vb.x; acc[5] += w * vb.y;
                acc[6] += w * vb.z; acc[7] += w * vb.w;
            }
        }
        const float bb = __ldg(&b1[o]);
        float4 r0, r1;
        r0.x = fmaxf(acc[0] + bb, 0.f); r0.y = fmaxf(acc[1] + bb, 0.f);
        r0.z = fmaxf(acc[2] + bb, 0.f); r0.w = fmaxf(acc[3] + bb, 0.f);
        r1.x = fmaxf(acc[4] + bb, 0.f); r1.y = fmaxf(acc[5] + bb, 0.f);
        r1.z = fmaxf(acc[6] + bb, 0.f); r1.w = fmaxf(acc[7] + bb, 0.f);
        *(float4*)&sH[o * SPAD + vh * 8]     = r0;
        *(float4*)&sH[o * SPAD + vh * 8 + 4] = r1;
    }
    __syncthreads();

    // ---- h2: thread = (c2 128, vq 4): vertices vq*4..+3 ----
    {
        const int c2 = tid >> 2, vq = tid & 3;
        float acc2[4] = {0.f, 0.f, 0.f, 0.f};
        const float4* w2r = (const float4*)(W2 + c2 * 256);
        #pragma unroll 2
        for (int k4 = 0; k4 < 64; ++k4) {
            const float4 w4 = __ldg(&w2r[k4]);
            #pragma unroll
            for (int u = 0; u < 4; ++u) {
                const int k = k4 * 4 + u;
                const float w = (u == 0) ? w4.x : (u == 1) ? w4.y
                              : (u == 2) ? w4.z : w4.w;
                const float4 va = *(const float4*)&sH[k * SPAD + vq * 4];
                acc2[0] += w * va.x; acc2[1] += w * va.y;
                acc2[2] += w * va.z; acc2[3] += w * va.w;
            }
        }
        __syncthreads();   // all h1 reads of sP done; reuse sP as h2T
        const float bb = __ldg(&b2[c2]);
        float4 rr;
        rr.x = fmaxf(acc2[0] + bb, 0.f); rr.y = fmaxf(acc2[1] + bb, 0.f);
        rr.z = fmaxf(acc2[2] + bb, 0.f); rr.w = fmaxf(acc2[3] + bb, 0.f);
        *(float4*)&sP[c2 * SPAD + vq * 4] = rr;
    }
    __syncthreads();

    // ---- heads ----
    if (tid < MBV * 4) {
        const int v = tid >> 2, hd = tid & 3;
        const float* wr; float bias;
        if      (hd == 0) { wr = Wa;       bias = __ldg(&ba[0]); }
        else if (hd == 1) { wr = Wa + 128; bias = __ldg(&ba[1]); }
        else if (hd == 2) { wr = Wr;       bias = __ldg(&br[0]); }
        else              { wr = Ww;       bias = __ldg(&bw[0]); }
        float s = bias;
        #pragma unroll 4
        for (int k = 0; k < 128; k++) s = fmaf(__ldg(&wr[k]), sP[k * SPAD + v], s);
        const int gidx = base + v;
        if      (hd <  2) out[gidx * 2 + hd] = s;
        else if (hd == 2) out[2 * BN + gidx] = s;
        else              out[3 * BN + gidx] = s;
    }
}

// ============================================================================
extern "C" void kernel_launch(void* const* d_in, const int* in_sizes, int n_in,
                              void* d_out, int out_size)
{
    const float* features = (const float*)d_in[0];
    const float* vertices = (const float*)d_in[1];
    const float* Wc = (const float*)d_in[2];
    const float* bc = (const float*)d_in[3];
    const float* W1 = (const float*)d_in[4];
    const float* b1 = (const float*)d_in[5];
    const float* W2 = (const float*)d_in[6];
    const float* b2 = (const float*)d_in[7];
    const float* Wa = (const float*)d_in[8];
    const float* ba = (const float*)d_in[9];
    const float* Wr = (const float*)d_in[10];
    const float* br = (const float*)d_in[11];
    const float* Ww = (const float*)d_in[12];
    const float* bw = (const float*)d_in[13];
    float* out = (float*)d_out;

    cudaFuncSetAttribute(gemm_kernel, cudaFuncAttributeMaxDynamicSharedMemorySize, GEMM_SMEM);

    gemm_kernel<<<GRID_GEMM, 512, GEMM_SMEM>>>(features, Wc);
    gather_pool_kernel<<<BN, 128>>>(vertices, bc);
    mlp_kernel<<<BN / MBV, 512, (128 + 256) * SPAD * 4>>>(W1, b1, W2, b2, Wa, ba, Wr, br, Ww, bw, out);
}

// round 17
// speedup vs baseline: 1.0902x; 1.0864x over previous
#include <cuda_runtime.h>
#include <cstdint>

#define W_  256
#define H_  256
#define C_  256
#define HW_ 65536
#define B_  4
#define BN  4096
#define OC  128
#define NT  256
#define NTILES 1024            // B_*HW_/NT
#define GRID_GEMM 148
#define AFRAG_BYTES 131072
#define CHUNK_BYTES 32768      // 32k x 256hw x 4B
#define GEMM_SMEM (AFRAG_BYTES + 3*CHUNK_BYTES)   // 229376

__device__ float g_G[(size_t)B_ * HW_ * OC];   // [b][hw][o]
__device__ float g_pooled[BN * OC];

__device__ __forceinline__ uint32_t f2tf(float x) {
    uint32_t r; asm("cvt.rna.tf32.f32 %0, %1;" : "=r"(r) : "f"(x)); return r;
}
__device__ __forceinline__ uint32_t s2u(const void* p) {
    uint32_t a;
    asm("{ .reg .u64 t; cvta.to.shared.u64 t, %1; cvt.u32.u64 %0, t; }" : "=r"(a) : "l"(p));
    return a;
}
__device__ __forceinline__ void mma8(float* d, uint4 a, uint32_t b0, uint32_t b1) {
    asm volatile("mma.sync.aligned.m16n8k8.row.col.f32.tf32.tf32.f32 "
        "{%0,%1,%2,%3}, {%4,%5,%6,%7}, {%8,%9}, {%0,%1,%2,%3};"
        : "+f"(d[0]), "+f"(d[1]), "+f"(d[2]), "+f"(d[3])
        : "r"(a.x), "r"(a.y), "r"(a.z), "r"(a.w), "r"(b0), "r"(b1));
}

// issue one k32 x hw256 feature chunk via cp.async (XOR-swizzled), commit group.
__device__ __forceinline__ void issue_chunk(const float* __restrict__ f,
                                            int t, int c, uint32_t dst_base, int tid)
{
    if (t < NTILES) {
        const int b = t >> 8, hw0 = (t & 255) * NT;
        const int row = tid >> 4;
        const int col0 = (tid & 15) * 16;
        const float* src = f + ((size_t)(b * C_ + c * 32 + row)) * HW_ + hw0 + col0;
        #pragma unroll
        for (int j = 0; j < 4; j++) {
            const int col  = col0 + j * 4;
            const int colp = col ^ ((row & 3) << 3);
            const uint32_t dst = dst_base + ((uint32_t)(row * 256 + colp)) * 4u;
            asm volatile("cp.async.cg.shared.global [%0], [%1], 16;"
                         :: "r"(dst), "l"(src + j * 4) : "memory");
        }
    }
    asm volatile("cp.async.commit_group;" ::: "memory");
}

// ============================================================================
// GEMM (R13 config, measured 138.9/139.0us): 512 threads, CTA m128 x n256,
// warp tile m64 x n32. A frags in smem; B cp.async 3-stage ring.
// ============================================================================
__global__ __launch_bounds__(512, 1)
void gemm_kernel(const float* __restrict__ features, const float* __restrict__ Wc)
{
    extern __shared__ __align__(16) char dsm[];
    const uint32_t bs_u = s2u(dsm) + AFRAG_BYTES;

    const int tid = threadIdx.x, wid = tid >> 5, lane = tid & 31;
    const int g = lane >> 2, t4 = lane & 3;
    const int mg = wid & 1, ng = wid >> 1;        // m-group (o 64), n-group (hw 32)

    int tn = blockIdx.x, cn = 0;
    #pragma unroll
    for (int i = 0; i < 3; i++) {
        issue_chunk(features, tn, cn, bs_u + i * CHUNK_BYTES, tid);
        if (++cn == 8) { cn = 0; tn += GRID_GEMM; }
    }

    if (wid < 8) {
        const int o0 = wid * 16;
        for (int k = 0; k < 32; k++) {
            uint4 a;
            a.x = f2tf(__ldg(&Wc[(o0 + g    ) * 256 + k * 8 + t4    ]));
            a.y = f2tf(__ldg(&Wc[(o0 + g + 8) * 256 + k * 8 + t4    ]));
            a.z = f2tf(__ldg(&Wc[(o0 + g    ) * 256 + k * 8 + t4 + 4]));
            a.w = f2tf(__ldg(&Wc[(o0 + g + 8) * 256 + k * 8 + t4 + 4]));
            *(uint4*)(dsm + (((k * 8 + wid) * 32) + lane) * 16) = a;
        }
    }

    int bufi = 0;
    for (int t = blockIdx.x; t < NTILES; t += GRID_GEMM) {
        float acc[4][4][4];
        #pragma unroll
        for (int mi = 0; mi < 4; mi++)
            #pragma unroll
            for (int ni = 0; ni < 4; ni++)
                #pragma unroll
                for (int q = 0; q < 4; q++) acc[mi][ni][q] = 0.f;

        #pragma unroll
        for (int c = 0; c < 8; c++) {
            asm volatile("cp.async.wait_group 2;" ::: "memory");
            __syncthreads();
            const float* bb = (const float*)(dsm + AFRAG_BYTES + bufi * CHUNK_BYTES);
            #pragma unroll
            for (int kkl = 0; kkl < 4; kkl++) {
                const int ka = c * 4 + kkl;
                uint4 a[4];
                #pragma unroll
                for (int mi = 0; mi < 4; mi++)
                    a[mi] = *(const uint4*)(dsm + ((ka * 8 + mg * 4 + mi) * 32 + lane) * 16);
                #pragma unroll
                for (int ni = 0; ni < 4; ni++) {
                    const int colp = (ng * 32 + ni * 8 + g) ^ (t4 << 3);
                    const uint32_t b0 = f2tf(bb[(kkl * 8 + t4    ) * 256 + colp]);
                    const uint32_t b1 = f2tf(bb[(kkl * 8 + t4 + 4) * 256 + colp]);
                    #pragma unroll
                    for (int mi = 0; mi < 4; mi++) mma8(acc[mi][ni], a[mi], b0, b1);
                }
            }
            __syncthreads();
            issue_chunk(features, tn, cn, bs_u + bufi * CHUNK_BYTES, tid);
            if (++cn == 8) { cn = 0; tn += GRID_GEMM; }
            bufi = (bufi == 2) ? 0 : bufi + 1;
        }
        {
            const int b = t >> 8, hw0 = (t & 255) * NT;
            float* gb = g_G + (size_t)b * HW_ * OC;
            #pragma unroll
            for (int mi = 0; mi < 4; mi++)
                #pragma unroll
                for (int ni = 0; ni < 4; ni++) {
                    const int o  = mg * 64 + mi * 16 + g;
                    const int hw = hw0 + ng * 32 + ni * 8 + 2 * t4;
                    float* p = gb + (size_t)hw * OC + o;
                    p[0]      = acc[mi][ni][0];
                    p[OC]     = acc[mi][ni][1];
                    p[8]      = acc[mi][ni][2];
                    p[OC + 8] = acc[mi][ni][3];
                }
        }
    }
}

// ============================================================================
// Gather: bilinear on G + bias + relu + 7x7 mean. Block = vertex, thread = o.
// ============================================================================
__global__ __launch_bounds__(128)
void gather_pool_kernel(const float* __restrict__ vertices, const float* __restrict__ bc)
{
    const int bid = blockIdx.x, o = threadIdx.x, b = bid >> 10;
    const float fx = vertices[bid * 2] - 3.5f, fy = vertices[bid * 2 + 1] - 3.5f;
    int ix = (int)floorf(fx), iy = (int)floorf(fy);
    const float lx = fx - ix, ly = fy - iy;
    ix = max(0, min(ix, W_ - 8)); iy = max(0, min(iy, H_ - 8));
    const float hx = 1.f - lx, hy = 1.f - ly;
    const float w00 = hy * hx, w01 = hy * lx, w10 = ly * hx, w11 = ly * lx;
    const float bias = __ldg(&bc[o]);

    const float* base = g_G + ((size_t)b * HW_ + (size_t)iy * W_ + ix) * OC + o;
    float prev[8], cur[8], acc = 0.f;
    #pragma unroll
    for (int r = 0; r < 8; r++) {
        #pragma unroll
        for (int c = 0; c < 8; c++) cur[c] = __ldg(base + ((size_t)r * W_ + c) * OC);
        if (r > 0) {
            #pragma unroll
            for (int px = 0; px < 7; px++) {
                const float v = w00 * prev[px] + w01 * prev[px + 1]
                              + w10 * cur[px]  + w11 * cur[px + 1] + bias;
                acc += fmaxf(v, 0.f);
            }
        }
        #pragma unroll
        for (int c = 0; c < 8; c++) prev[c] = cur[c];
    }
    g_pooled[bid * OC + o] = acc * (1.0f / 49.0f);
}

// ============================================================================
// MLP + heads (R10 config, measured 39.9us). 32 vertices/block (128 blocks),
// 256 threads. h1: 4 outputs x 8 vertices; h2: 4 x 4. smem 55,296 B dynamic.
// ============================================================================
#define MBV 32
#define SPAD 36
__global__ __launch_bounds__(256)
void mlp_kernel(const float* __restrict__ W1, const float* __restrict__ b1,
                const float* __restrict__ W2, const float* __restrict__ b2,
                const float* __restrict__ Wa, const float* __restrict__ ba,
                const float* __restrict__ Wr, const float* __restrict__ br,
                const float* __restrict__ Ww, const float* __restrict__ bw,
                float* __restrict__ out)
{
    extern __shared__ __align__(16) float ms[];
    float* sP = ms;                 // [128][SPAD] pooled (k-major), later h2T
    float* sH = ms + 128 * SPAD;    // [256][SPAD] h1T

    const int tid = threadIdx.x, base = blockIdx.x * MBV;

    for (int e = tid; e < MBV * 128; e += 256) {
        const int v = e >> 7, k = e & 127;
        sP[k * SPAD + v] = g_pooled[(base + v) * 128 + k];
    }
    __syncthreads();

    // ---- h1: thread = (oq 64, vq 4): outputs oq*4..+3, vertices vq*8..+7 ----
    {
        const int oq = tid >> 2, vq = tid & 3;
        float acc[4][8];
        #pragma unroll
        for (int r = 0; r < 4; r++)
            #pragma unroll
            for (int j = 0; j < 8; j++) acc[r][j] = 0.f;
        #pragma unroll 2
        for (int k4 = 0; k4 < 32; ++k4) {
            float4 wv[4];
            #pragma unroll
            for (int r = 0; r < 4; r++)
                wv[r] = __ldg((const float4*)(W1 + (oq * 4 + r) * 128 + k4 * 4));
            #pragma unroll
            for (int u = 0; u < 4; ++u) {
                const int k = k4 * 4 + u;
                const float4 va = *(const float4*)&sP[k * SPAD + vq * 8];
                const float4 vb = *(const float4*)&sP[k * SPAD + vq * 8 + 4];
                #pragma unroll
                for (int r = 0; r < 4; r++) {
                    const float w = (u == 0) ? wv[r].x : (u == 1) ? wv[r].y
                                  : (u == 2) ? wv[r].z : wv[r].w;
                    acc[r][0] += w * va.x; acc[r][1] += w * va.y;
                    acc[r][2] += w * va.z; acc[r][3] += w * va.w;
                    acc[r][4] += w * vb.x; acc[r][5] += w * vb.y;
                    acc[r][6] += w * vb.z; acc[r][7] += w * vb.w;
                }
            }
        }
        #pragma unroll
        for (int r = 0; r < 4; r++) {
            const int o = oq * 4 + r;
            const float bb = __ldg(&b1[o]);
            float4 r0, r1;
            r0.x = fmaxf(acc[r][0] + bb, 0.f); r0.y = fmaxf(acc[r][1] + bb, 0.f);
            r0.z = fmaxf(acc[r][2] + bb, 0.f); r0.w = fmaxf(acc[r][3] + bb, 0.f);
            r1.x = fmaxf(acc[r][4] + bb, 0.f); r1.y = fmaxf(acc[r][5] + bb, 0.f);
            r1.z = fmaxf(acc[r][6] + bb, 0.f); r1.w = fmaxf(acc[r][7] + bb, 0.f);
            *(float4*)&sH[o * SPAD + vq * 8]     = r0;
            *(float4*)&sH[o * SPAD + vq * 8 + 4] = r1;
        }
    }
    __syncthreads();

    // ---- h2: thread = (oq2 32, vq2 8): outputs oq2*4..+3, vertices vq2*4..+3 ----
    {
        const int oq2 = tid >> 3, vq2 = tid & 7;
        float acc2[4][4];
        #pragma unroll
        for (int r = 0; r < 4; r++)
            #pragma unroll
            for (int j = 0; j < 4; j++) acc2[r][j] = 0.f;
        #pragma unroll 2
        for (int k4 = 0; k4 < 64; ++k4) {
            float4 wv[4];
            #pragma unroll
            for (int r = 0; r < 4; r++)
                wv[r] = __ldg((const float4*)(W2 + (oq2 * 4 + r) * 256 + k4 * 4));
            #pragma unroll
            for (int u = 0; u < 4; ++u) {
                const int k = k4 * 4 + u;
                const float4 va = *(const float4*)&sH[k * SPAD + vq2 * 4];
                #pragma unroll
                for (int r = 0; r < 4; r++) {
                    const float w = (u == 0) ? wv[r].x : (u == 1) ? wv[r].y
                                  : (u == 2) ? wv[r].z : wv[r].w;
                    acc2[r][0] += w * va.x; acc2[r][1] += w * va.y;
                    acc2[r][2] += w * va.z; acc2[r][3] += w * va.w;
                }
            }
        }
        __syncthreads();   // all h1 reads of sP done; reuse sP as h2T
        #pragma unroll
        for (int r = 0; r < 4; r++) {
            const int o = oq2 * 4 + r;
            const float bb = __ldg(&b2[o]);
            float4 rr;
            rr.x = fmaxf(acc2[r][0] + bb, 0.f); rr.y = fmaxf(acc2[r][1] + bb, 0.f);
            rr.z = fmaxf(acc2[r][2] + bb, 0.f); rr.w = fmaxf(acc2[r][3] + bb, 0.f);
            *(float4*)&sP[o * SPAD + vq2 * 4] = rr;
        }
    }
    __syncthreads();

    // ---- heads ----
    if (tid < MBV * 4) {
        const int v = tid >> 2, hd = tid & 3;
        const float* wr; float bias;
        if      (hd == 0) { wr = Wa;       bias = __ldg(&ba[0]); }
        else if (hd == 1) { wr = Wa + 128; bias = __ldg(&ba[1]); }
        else if (hd == 2) { wr = Wr;       bias = __ldg(&br[0]); }
        else              { wr = Ww;       bias = __ldg(&bw[0]); }
        float s = bias;
        #pragma unroll 4
        for (int k = 0; k < 128; k++) s = fmaf(__ldg(&wr[k]), sP[k * SPAD + v], s);
        const int gidx = base + v;
        if      (hd <  2) out[gidx * 2 + hd] = s;
        else if (hd == 2) out[2 * BN + gidx] = s;
        else              out[3 * BN + gidx] = s;
    }
}

// ============================================================================
extern "C" void kernel_launch(void* const* d_in, const int* in_sizes, int n_in,
                              void* d_out, int out_size)
{
    const float* features = (const float*)d_in[0];
    const float* vertices = (const float*)d_in[1];
    const float* Wc = (const float*)d_in[2];
    const float* bc = (const float*)d_in[3];
    const float* W1 = (const float*)d_in[4];
    const float* b1 = (const float*)d_in[5];
    const float* W2 = (const float*)d_in[6];
    const float* b2 = (const float*)d_in[7];
    const float* Wa = (const float*)d_in[8];
    const float* ba = (const float*)d_in[9];
    const float* Wr = (const float*)d_in[10];
    const float* br = (const float*)d_in[11];
    const float* Ww = (const float*)d_in[12];
    const float* bw = (const float*)d_in[13];
    float* out = (float*)d_out;

    cudaFuncSetAttribute(gemm_kernel, cudaFuncAttributeMaxDynamicSharedMemorySize, GEMM_SMEM);
    cudaFuncSetAttribute(mlp_kernel,  cudaFuncAttributeMaxDynamicSharedMemorySize,
                         (128 + 256) * SPAD * 4);

    gemm_kernel<<<GRID_GEMM, 512, GEMM_SMEM>>>(features, Wc);
    gather_pool_kernel<<<BN, 128>>>(vertices, bc);
    mlp_kernel<<<BN / MBV, 256, (128 + 256) * SPAD * 4>>>(W1, b1, W2, b2, Wa, ba, Wr, br, Ww, bw, out);
}